// round 6
// baseline (speedup 1.0000x reference)
#include <cuda_runtime.h>

#define Bb 8
#define Ss 384
#define HIDD 512
#define NHh 8
#define HDd 64
#define RR (Bb*Ss)            // 3072 rows
#define ISCALE 0.044194173824159216f  // 1/sqrt(512)

// ---- scratch (device globals; no allocation allowed) ----
static __device__ __align__(16) unsigned g_af[192*64*128];   // enc A-frags [rblk192][kk64][128]
static __device__ __align__(16) unsigned g_wf[4*64*64*64];   // W B-frags  [mat4][nb64][kk64][64]
static __device__ __align__(16) unsigned g_qf[NHh*RR*HDd];   // Q A-frags  [h][rblk192][kk8][128]
static __device__ __align__(16) unsigned g_kf[NHh*RR*HDd];   // K B-frags  [h][kt48][nb8][kk8][64]
static __device__ __align__(16) unsigned g_vf[NHh*RR*HDd];   // V B-frags  [h][kt48][db8][kk8][64]
static __device__ __align__(16) unsigned g_cf[192*64*128];   // ctx A-frags [rblk192][kk64][128]
static __device__ float g_tmp[RR*HIDD];

__device__ __forceinline__ unsigned f2tf32(float x) {
    unsigned u; asm("cvt.rna.tf32.f32 %0, %1;" : "=r"(u) : "f"(x)); return u;
}

__device__ __forceinline__ void mma_tf32(float d[4], uint4 a, uint2 b) {
    asm volatile(
      "mma.sync.aligned.m16n8k8.row.col.f32.tf32.tf32.f32 "
      "{%0,%1,%2,%3}, {%4,%5,%6,%7}, {%8,%9}, {%0,%1,%2,%3};\n"
      : "+f"(d[0]), "+f"(d[1]), "+f"(d[2]), "+f"(d[3])
      : "r"(a.x), "r"(a.y), "r"(a.z), "r"(a.w), "r"(b.x), "r"(b.y));
}

__device__ __forceinline__ void cp16(unsigned dst_smem, const void* src) {
    asm volatile("cp.async.cg.shared.global [%0], [%1], 16;\n"
                 :: "r"(dst_smem), "l"(src));
}
#define CP_COMMIT asm volatile("cp.async.commit_group;\n" ::: "memory")
#define CP_WAIT1  asm volatile("cp.async.wait_group 1;\n" ::: "memory")
#define CP_WAIT0  asm volatile("cp.async.wait_group 0;\n" ::: "memory")

// ============================================================
// Kernel 0: convert enc -> A-frags, Wq/Wk/Wv/Wo -> B-frags (once).
// ============================================================
__global__ __launch_bounds__(256) void prep_kernel(
    const float* __restrict__ enc, const float* __restrict__ Wq,
    const float* __restrict__ Wk,  const float* __restrict__ Wv,
    const float* __restrict__ Wo)
{
    __shared__ float Ts[64][68];
    int tid = threadIdx.x, lane = tid & 31;
    int bid = blockIdx.x;

    if (bid < 384) {
        int m0 = (bid >> 3) * 64, k0 = (bid & 7) * 64;
        int r = tid >> 2;
        #pragma unroll
        for (int i = 0; i < 4; i++) {
            int c = ((tid & 3) + 4*i) * 4;
            *(float4*)&Ts[r][c] = *(const float4*)(enc + (size_t)(m0 + r)*HIDD + k0 + c);
        }
        __syncthreads();
        #pragma unroll
        for (int i = 0; i < 4; i++) {
            int f = (tid >> 5) + 8*i;
            int rblk = f >> 3, kk = f & 7;
            unsigned a[4];
            #pragma unroll
            for (int rg = 0; rg < 4; rg++) {
                int rr = (lane >> 2) + 8*(rg & 1);
                int kb = (lane & 3) + 4*(rg >> 1);
                a[rg] = f2tf32(Ts[rblk*16 + rr][kk*8 + kb]);
            }
            size_t idx = ((size_t)((m0 >> 4) + rblk) * 64 + (k0 >> 3) + kk) * 128 + lane*4;
            *(uint4*)&g_af[idx] = make_uint4(a[0], a[1], a[2], a[3]);
        }
    } else {
        int wb2 = bid - 384;
        int mat = wb2 >> 6, t64 = wb2 & 63;
        int n0 = (t64 >> 3) * 64, k0 = (t64 & 7) * 64;
        const float* W = (mat == 0) ? Wq : (mat == 1) ? Wk : (mat == 2) ? Wv : Wo;
        int r = tid >> 2;
        #pragma unroll
        for (int i = 0; i < 4; i++) {
            int c = ((tid & 3) + 4*i) * 4;
            *(float4*)&Ts[r][c] = *(const float4*)(W + (size_t)(n0 + r)*HIDD + k0 + c);
        }
        __syncthreads();
        #pragma unroll
        for (int i = 0; i < 8; i++) {
            int f = (tid >> 5) + 8*i;
            int nb = f >> 3, kk = f & 7;
            unsigned b[2];
            #pragma unroll
            for (int rg = 0; rg < 2; rg++) {
                int nn = lane >> 2;
                int kb = (lane & 3) + 4*rg;
                b[rg] = f2tf32(Ts[nb*8 + nn][kk*8 + kb]);
            }
            size_t idx = ((size_t)(mat*64 + (n0 >> 3) + nb) * 64 + (k0 >> 3) + kk) * 64 + lane*2;
            *(uint2*)&g_wf[idx] = make_uint2(b[0], b[1]);
        }
    }
}

// ============================================================
// Pipelined 128x64x512 GEMM core: 16 chunks of 4 kk, cp.async
// double-buffered. Each warp: 16 rows x 64 cols = 8 accumulators.
// sA: 2 x 4096 words, sW: 2 x 2048 words  (48 KB total)
// ============================================================
__device__ __forceinline__ void gemm_pipe(
    const unsigned* __restrict__ abase, const unsigned* __restrict__ wbase,
    unsigned* sA, unsigned* sW, float facc[8][4],
    int tid, int lane, int wr)
{
    auto stage = [&](int c, int buf) {
        #pragma unroll
        for (int s = 0; s < 4; s++) {
            int u = tid + 256*s;                  // uint4 idx 0..1023
            int rblk = u >> 7, kk = (u >> 5) & 3, l = u & 31;
            unsigned dst = (unsigned)__cvta_generic_to_shared(sA + buf*4096 + u*4);
            cp16(dst, abase + (size_t)(rblk*64 + c*4 + kk)*128 + l*4);
        }
        #pragma unroll
        for (int s = 0; s < 2; s++) {
            int u = tid + 256*s;                  // uint4 idx 0..511
            int nb = u >> 6, kk = (u >> 4) & 3, l = u & 15;
            unsigned dst = (unsigned)__cvta_generic_to_shared(sW + buf*2048 + u*4);
            cp16(dst, wbase + (size_t)(nb*64 + c*4 + kk)*64 + l*4);
        }
        CP_COMMIT;
    };

    stage(0, 0);
    for (int c = 0; c < 16; c++) {
        __syncthreads();
        if (c + 1 < 16) { stage(c + 1, (c + 1) & 1); CP_WAIT1; }
        else            { CP_WAIT0; }
        __syncthreads();
        const unsigned* A = sA + (c & 1) * 4096;
        const unsigned* W = sW + (c & 1) * 2048;
        #pragma unroll
        for (int kk = 0; kk < 4; kk++) {
            uint4 aa = *(const uint4*)(A + ((wr*4 + kk)*32 + lane)*4);
            #pragma unroll
            for (int nt = 0; nt < 8; nt++) {
                uint2 bb = *(const uint2*)(W + nt*256 + kk*64 + lane*2);
                mma_tf32(facc[nt], aa, bb);
            }
        }
    }
}

// ============================================================
// Kernel 1: Q/K/V projections (pipelined GEMM + frag scatter)
// grid (8 heads, 24 m-tiles of 128, 3 matrices), block 256
// ============================================================
__global__ __launch_bounds__(256) void qkv_kernel()
{
    extern __shared__ unsigned dsm[];
    unsigned* sA = dsm;           // 2 x 4096
    unsigned* sW = dsm + 8192;    // 2 x 2048

    int h = blockIdx.x, m0 = blockIdx.y * 128, z = blockIdx.z;
    int tid = threadIdx.x, lane = tid & 31, wr = tid >> 5;

    float facc[8][4] = {};
    gemm_pipe(g_af + (size_t)(m0 >> 4)*64*128,
              g_wf + (size_t)(z*64 + h*8)*64*64,
              sA, sW, facc, tid, lane, wr);

    unsigned* outp = (z == 0) ? g_qf : ((z == 1) ? g_kf : g_vf);
    int q2 = lane & 3, r4 = lane >> 2;
    #pragma unroll
    for (int nt = 0; nt < 8; nt++) {
        #pragma unroll
        for (int hi = 0; hi < 2; hi++) {
            #pragma unroll
            for (int j = 0; j < 2; j++) {
                unsigned tv = f2tf32(facc[nt][2*hi + j]);
                int d = nt*8 + 2*q2 + j;
                int gr = m0 + 16*wr + r4 + 8*hi;
                size_t idx;
                if (z == 0) {                   // Q: A-frag
                    idx = ((size_t)(h*192 + (gr >> 4))*8 + (d >> 3))*128
                        + (size_t)(4*r4 + (d & 3))*4 + hi + 2*((d >> 2) & 1);
                } else if (z == 1) {            // K: B-frag (n=key, k=d)
                    int kt = gr >> 6, rk = gr & 63;
                    idx = (size_t)(h*48 + kt)*4096
                        + ((size_t)((rk >> 3)*8 + (d >> 3))*32 + 4*(rk & 7) + (d & 3))*2
                        + ((d >> 2) & 1);
                } else {                        // V: B-frag (n=d, k=key)
                    int kt = gr >> 6, rk = gr & 63;
                    idx = (size_t)(h*48 + kt)*4096
                        + ((size_t)((d >> 3)*8 + (rk >> 3))*32 + 4*(d & 7) + (rk & 3))*2
                        + ((rk >> 2) & 1);
                }
                outp[idx] = tv;
            }
        }
    }
}

// ============================================================
// Kernel 2: attention, 128-row q-tiles, 8 warps x (16 rows, 64 cols).
// Register row-sums (no atomics). Class-balanced bid map.
// grid 192 blocks, 256 thr, dyn smem 101376 B
// ============================================================
__global__ __launch_bounds__(256, 2) void attn_kernel(float* __restrict__ w_out)
{
    extern __shared__ unsigned dsm[];
    unsigned* KV = dsm;                               // 2 bufs x 8192 (K | V)
    float (*Ps)[68] = (float(*)[68])(dsm + 16384);    // 128 x 68
    float* ls  = (float*)(dsm + 16384) + 128*68;
    float* lrl = ls + 128;

    int tid = threadIdx.x, lane = tid & 31, wr = tid >> 5;
    int bid = blockIdx.x;

    // class-balanced mapping: heavy(st=2) singles, light+med pairs
    int st, idx;
    if      (bid < 44)  { st = 0; idx = bid; }
    else if (bid < 84)  { st = 1; idx = bid - 44; }
    else if (bid < 148) { st = 2; idx = bid - 84; }
    else if (bid < 168) { st = 0; idx = 44 + (bid - 148); }
    else                { st = 1; idx = 40 + (bid - 168); }
    int h = idx & 7, bq = idx >> 3;
    int s0 = st * 128;
    int r0 = bq * Ss + s0;
    int nj = 2*st + 2, nv = 8 * nj;

    int q2 = lane & 3, r4 = lane >> 2;
    int rlo = 16*wr + r4;
    int lrr = tid >> 4, lcc = (tid & 15) * 4;

    // zero masked w tiles up front
    for (int kb = 0; kb < 8; kb++) {
        size_t wrow = ((size_t)((bq*NHh + h)*Bb + kb)) * Ss + s0;
        for (int j = nj; j < 6; j++) {
            float4 z = make_float4(0.f, 0.f, 0.f, 0.f);
            #pragma unroll
            for (int i = 0; i < 8; i++)
                *(float4*)(w_out + (wrow + lrr + 16*i) * Ss + j*64 + lcc) = z;
        }
    }

    // Q fragments resident in registers (16 rows x 64 k per warp)
    uint4 qa[8];
    const unsigned* qb = g_qf + (size_t)((h*192 + (r0 >> 4) + wr)*8)*128;
    #pragma unroll
    for (int kk = 0; kk < 8; kk++) qa[kk] = *(const uint4*)(qb + kk*128 + lane*4);

    auto stageK = [&](int v, int buf) {
        int kt = (v / nj)*6 + (v % nj);
        const unsigned* src = g_kf + (size_t)(h*48 + kt)*4096;
        #pragma unroll
        for (int s = 0; s < 4; s++) {
            unsigned dst = (unsigned)__cvta_generic_to_shared(KV + buf*8192 + s*1024 + tid*4);
            cp16(dst, src + s*1024 + tid*4);
        }
        CP_COMMIT;
    };
    auto stageKV = [&](int v, int buf) {
        int kt = (v / nj)*6 + (v % nj);
        const unsigned* ks = g_kf + (size_t)(h*48 + kt)*4096;
        const unsigned* vs = g_vf + (size_t)(h*48 + kt)*4096;
        #pragma unroll
        for (int s = 0; s < 4; s++) {
            unsigned dk = (unsigned)__cvta_generic_to_shared(KV + buf*8192 + s*1024 + tid*4);
            unsigned dv = (unsigned)__cvta_generic_to_shared(KV + buf*8192 + 4096 + s*1024 + tid*4);
            cp16(dk, ks + s*1024 + tid*4);
            cp16(dv, vs + s*1024 + tid*4);
        }
        CP_COMMIT;
    };

    // -------- phase A: row sums in registers --------
    float l_lo = 0.f, l_hi = 0.f;
    stageK(0, 0);
    for (int v = 0; v < nv; v++) {
        __syncthreads();
        if (v + 1 < nv) { stageK(v + 1, (v + 1) & 1); CP_WAIT1; }
        else            { CP_WAIT0; }
        __syncthreads();
        const unsigned* Kf = KV + (v & 1)*8192;
        int j = v % nj;
        int kp0 = j * 64;
        bool needmask = (j >= nj - 2);

        #pragma unroll
        for (int g = 0; g < 2; g++) {
            float sacc[4][4] = {};
            #pragma unroll
            for (int kk = 0; kk < 8; kk++) {
                #pragma unroll
                for (int t = 0; t < 4; t++) {
                    uint2 bb = *(const uint2*)(Kf + ((g*4 + t)*8 + kk)*64 + lane*2);
                    mma_tf32(sacc[t], qa[kk], bb);
                }
            }
            #pragma unroll
            for (int t = 0; t < 4; t++) {
                int cb = (g*4 + t)*8 + 2*q2;
                float p0 = __expf(sacc[t][0] * ISCALE);
                float p1 = __expf(sacc[t][1] * ISCALE);
                float p2 = __expf(sacc[t][2] * ISCALE);
                float p3 = __expf(sacc[t][3] * ISCALE);
                if (needmask) {
                    int kp = kp0 + cb, qpl = s0 + rlo, qph = qpl + 8;
                    if (kp     > qpl) p0 = 0.f;
                    if (kp + 1 > qpl) p1 = 0.f;
                    if (kp     > qph) p2 = 0.f;
                    if (kp + 1 > qph) p3 = 0.f;
                }
                l_lo += p0 + p1; l_hi += p2 + p3;
            }
        }
    }
    l_lo += __shfl_xor_sync(0xffffffffu, l_lo, 1);
    l_lo += __shfl_xor_sync(0xffffffffu, l_lo, 2);
    l_hi += __shfl_xor_sync(0xffffffffu, l_hi, 1);
    l_hi += __shfl_xor_sync(0xffffffffu, l_hi, 2);
    if (q2 == 0) { ls[rlo] = l_lo; ls[rlo + 8] = l_hi; }
    __syncthreads();
    if (tid < 128) lrl[tid] = -__logf(ls[tid]);
    __syncthreads();
    float la = lrl[rlo], lb = lrl[rlo + 8];

    // -------- phase B: normalized w + PV --------
    float cacc[8][4] = {};
    stageKV(0, 0);
    for (int v = 0; v < nv; v++) {
        __syncthreads();            // prev readers of KV buf + Ps done
        if (v + 1 < nv) { stageKV(v + 1, (v + 1) & 1); CP_WAIT1; }
        else            { CP_WAIT0; }
        __syncthreads();
        const unsigned* Kf = KV + (v & 1)*8192;
        const unsigned* Vf = Kf + 4096;
        int j = v % nj, kb = v / nj;
        int kp0 = j * 64;
        bool needmask = (j >= nj - 2);

        #pragma unroll
        for (int g = 0; g < 2; g++) {
            float sacc[4][4] = {};
            #pragma unroll
            for (int kk = 0; kk < 8; kk++) {
                #pragma unroll
                for (int t = 0; t < 4; t++) {
                    uint2 bb = *(const uint2*)(Kf + ((g*4 + t)*8 + kk)*64 + lane*2);
                    mma_tf32(sacc[t], qa[kk], bb);
                }
            }
            #pragma unroll
            for (int t = 0; t < 4; t++) {
                int cb = (g*4 + t)*8 + 2*q2;
                float p0 = __expf(fmaf(sacc[t][0], ISCALE, la));
                float p1 = __expf(fmaf(sacc[t][1], ISCALE, la));
                float p2 = __expf(fmaf(sacc[t][2], ISCALE, lb));
                float p3 = __expf(fmaf(sacc[t][3], ISCALE, lb));
                if (needmask) {
                    int kp = kp0 + cb, qpl = s0 + rlo, qph = qpl + 8;
                    if (kp     > qpl) p0 = 0.f;
                    if (kp + 1 > qpl) p1 = 0.f;
                    if (kp     > qph) p2 = 0.f;
                    if (kp + 1 > qph) p3 = 0.f;
                }
                *(float2*)&Ps[rlo][cb]     = make_float2(p0, p1);
                *(float2*)&Ps[rlo + 8][cb] = make_float2(p2, p3);
            }
        }
        __syncthreads();

        // coalesced normalized w write
        size_t wrow = ((size_t)((bq*NHh + h)*Bb + kb)) * Ss + s0;
        #pragma unroll
        for (int i = 0; i < 8; i++)
            *(float4*)(w_out + (wrow + lrr + 16*i) * Ss + kp0 + lcc) =
                *(float4*)&Ps[lrr + 16*i][lcc];

        // ctx += P V  (P as raw fp32 bits -> tf32 truncation)
        #pragma unroll
        for (int kk = 0; kk < 8; kk++) {
            int k0 = kk * 8;
            uint4 pa;
            pa.x = __float_as_uint(Ps[rlo    ][k0 + q2]);
            pa.y = __float_as_uint(Ps[rlo + 8][k0 + q2]);
            pa.z = __float_as_uint(Ps[rlo    ][k0 + 4 + q2]);
            pa.w = __float_as_uint(Ps[rlo + 8][k0 + 4 + q2]);
            #pragma unroll
            for (int nt = 0; nt < 8; nt++) {
                uint2 bb = *(const uint2*)(Vf + (nt*8 + kk)*64 + lane*2);
                mma_tf32(cacc[nt], pa, bb);
            }
        }
    }

    // ctx epilogue -> A-frag layout (already normalized)
    int rblkg = (r0 >> 4) + wr;
    #pragma unroll
    for (int nt = 0; nt < 8; nt++) {
        size_t kkg = (size_t)(h*8 + nt);
        #pragma unroll
        for (int hi = 0; hi < 2; hi++) {
            #pragma unroll
            for (int j = 0; j < 2; j++) {
                int kbit = 2*q2 + j;
                int word = (4*r4 + (kbit & 3))*4 + hi + 2*((kbit >> 2) & 1);
                g_cf[((size_t)rblkg*64 + kkg)*128 + word] = f2tf32(cacc[nt][2*hi + j]);
            }
        }
    }
}

// ============================================================
// Kernel 3: out_pre = ctx @ Wo^T + enc -> g_tmp (pipelined GEMM)
// grid (8 n-tiles, 24 m-tiles of 128), block 256
// ============================================================
__global__ __launch_bounds__(256) void out_kernel(const float* __restrict__ enc)
{
    extern __shared__ unsigned dsm[];
    unsigned* sA = dsm;
    unsigned* sW = dsm + 8192;

    int n0 = blockIdx.x * 64, m0 = blockIdx.y * 128;
    int tid = threadIdx.x, lane = tid & 31, wr = tid >> 5;

    float facc[8][4] = {};
    gemm_pipe(g_cf + (size_t)(m0 >> 4)*64*128,
              g_wf + (size_t)(3*64 + (n0 >> 3))*64*64,
              sA, sW, facc, tid, lane, wr);

    int q2 = lane & 3, r4 = lane >> 2;
    #pragma unroll
    for (int nt = 0; nt < 8; nt++) {
        #pragma unroll
        for (int hi = 0; hi < 2; hi++) {
            int row = m0 + 16*wr + r4 + 8*hi;
            int col = n0 + nt*8 + 2*q2;
            float2 e2 = *(const float2*)(enc + (size_t)row * HIDD + col);
            float2 o = make_float2(facc[nt][2*hi] + e2.x, facc[nt][2*hi + 1] + e2.y);
            *(float2*)(g_tmp + (size_t)row * HIDD + col) = o;
        }
    }
}

// ============================================================
// Kernel 4: per-row LayerNorm -> d_out[0 : R*HID]
// ============================================================
__global__ __launch_bounds__(256) void ln_kernel(
    const float* __restrict__ gamma,
    const float* __restrict__ beta,
    float* __restrict__ out)
{
    int r = blockIdx.x;
    int t = threadIdx.x;
    const float* x = g_tmp + (size_t)r * HIDD;
    float v0 = x[t], v1 = x[t + 256];

    __shared__ float red[256];
    red[t] = v0 + v1;
    __syncthreads();
    #pragma unroll
    for (int o = 128; o > 0; o >>= 1) {
        if (t < o) red[t] += red[t + o];
        __syncthreads();
    }
    float mu = red[0] * (1.0f / HIDD);
    __syncthreads();

    float d0 = v0 - mu, d1 = v1 - mu;
    red[t] = d0*d0 + d1*d1;
    __syncthreads();
    #pragma unroll
    for (int o = 128; o > 0; o >>= 1) {
        if (t < o) red[t] += red[t + o];
        __syncthreads();
    }
    float var = red[0] * (1.0f / HIDD);
    float rs = rsqrtf(var + 1e-6f);

    out[(size_t)r * HIDD + t]       = d0 * rs * gamma[t]       + beta[t];
    out[(size_t)r * HIDD + t + 256] = d1 * rs * gamma[t + 256] + beta[t + 256];
}

// ============================================================
// launch
// ============================================================
extern "C" void kernel_launch(void* const* d_in, const int* in_sizes, int n_in,
                              void* d_out, int out_size)
{
    const float* enc   = (const float*)d_in[0];
    // d_in[1] = mask (int32 tril) — reproduced analytically
    const float* Wq    = (const float*)d_in[2];
    const float* Wk    = (const float*)d_in[3];
    const float* Wv    = (const float*)d_in[4];
    const float* Wo    = (const float*)d_in[5];
    const float* gamma = (const float*)d_in[6];
    const float* beta  = (const float*)d_in[7];

    float* out = (float*)d_out;                  // (B,S,HID)
    float* w   = out + (size_t)RR * HIDD;        // (B,NH,B,S,S)

    const int gemm_smem = (2*4096 + 2*2048) * 4;             // 49152 B
    const int attn_smem = 16384*4 + 128*68*4 + 256*4;        // 101376 B
    cudaFuncSetAttribute(qkv_kernel,  cudaFuncAttributeMaxDynamicSharedMemorySize, gemm_smem);
    cudaFuncSetAttribute(out_kernel,  cudaFuncAttributeMaxDynamicSharedMemorySize, gemm_smem);
    cudaFuncSetAttribute(attn_kernel, cudaFuncAttributeMaxDynamicSharedMemorySize, attn_smem);

    prep_kernel<<<640, 256>>>(enc, Wq, Wk, Wv, Wo);
    qkv_kernel<<<dim3(8, 24, 3), 256, gemm_smem>>>();
    attn_kernel<<<192, 256, attn_smem>>>(w);
    out_kernel<<<dim3(8, 24), 256, gemm_smem>>>(enc);
    ln_kernel<<<RR, 256>>>(gamma, beta, out);
}

// round 7
// speedup vs baseline: 1.3730x; 1.3730x over previous
#include <cuda_runtime.h>

#define Bb 8
#define Ss 384
#define HIDD 512
#define NHh 8
#define HDd 64
#define RR (Bb*Ss)            // 3072 rows
#define ISCALE 0.044194173824159216f  // 1/sqrt(512)

// ---- scratch (device globals; no allocation allowed) ----
static __device__ __align__(16) unsigned g_af[192*64*128];   // enc A-frags [rblk192][kk64][128]
static __device__ __align__(16) unsigned g_wf[4*64*64*64];   // W B-frags  [mat4][nb64][kk64][64]
static __device__ __align__(16) unsigned g_qf[NHh*RR*HDd];   // Q A-frags  [h][rblk192][kk8][128]
static __device__ __align__(16) unsigned g_kf[NHh*RR*HDd];   // K B-frags  [h][kt48][nb8][kk8][64]
static __device__ __align__(16) unsigned g_vf[NHh*RR*HDd];   // V B-frags  [h][kt48][db8][kk8][64]
static __device__ __align__(16) unsigned g_cf[192*64*128];   // ctx A-frags [rblk192][kk64][128]
static __device__ float g_tmp[RR*HIDD];

__device__ __forceinline__ unsigned f2tf32(float x) {
    unsigned u; asm("cvt.rna.tf32.f32 %0, %1;" : "=r"(u) : "f"(x)); return u;
}

__device__ __forceinline__ void mma_tf32(float d[4], uint4 a, uint2 b) {
    asm volatile(
      "mma.sync.aligned.m16n8k8.row.col.f32.tf32.tf32.f32 "
      "{%0,%1,%2,%3}, {%4,%5,%6,%7}, {%8,%9}, {%0,%1,%2,%3};\n"
      : "+f"(d[0]), "+f"(d[1]), "+f"(d[2]), "+f"(d[3])
      : "r"(a.x), "r"(a.y), "r"(a.z), "r"(a.w), "r"(b.x), "r"(b.y));
}

__device__ __forceinline__ void cp16(unsigned dst_smem, const void* src) {
    asm volatile("cp.async.cg.shared.global [%0], [%1], 16;\n"
                 :: "r"(dst_smem), "l"(src));
}
#define CP_COMMIT asm volatile("cp.async.commit_group;\n" ::: "memory")
#define CP_WAIT1  asm volatile("cp.async.wait_group 1;\n" ::: "memory")
#define CP_WAIT0  asm volatile("cp.async.wait_group 0;\n" ::: "memory")

// ============================================================
// Kernel 0: convert enc -> A-frags, Wq/Wk/Wv/Wo -> B-frags (once).
// ============================================================
__global__ __launch_bounds__(256) void prep_kernel(
    const float* __restrict__ enc, const float* __restrict__ Wq,
    const float* __restrict__ Wk,  const float* __restrict__ Wv,
    const float* __restrict__ Wo)
{
    __shared__ float Ts[64][68];
    int tid = threadIdx.x, lane = tid & 31;
    int bid = blockIdx.x;

    if (bid < 384) {
        int m0 = (bid >> 3) * 64, k0 = (bid & 7) * 64;
        int r = tid >> 2;
        #pragma unroll
        for (int i = 0; i < 4; i++) {
            int c = ((tid & 3) + 4*i) * 4;
            *(float4*)&Ts[r][c] = *(const float4*)(enc + (size_t)(m0 + r)*HIDD + k0 + c);
        }
        __syncthreads();
        #pragma unroll
        for (int i = 0; i < 4; i++) {
            int f = (tid >> 5) + 8*i;
            int rblk = f >> 3, kk = f & 7;
            unsigned a[4];
            #pragma unroll
            for (int rg = 0; rg < 4; rg++) {
                int rr = (lane >> 2) + 8*(rg & 1);
                int kb = (lane & 3) + 4*(rg >> 1);
                a[rg] = f2tf32(Ts[rblk*16 + rr][kk*8 + kb]);
            }
            size_t idx = ((size_t)((m0 >> 4) + rblk) * 64 + (k0 >> 3) + kk) * 128 + lane*4;
            *(uint4*)&g_af[idx] = make_uint4(a[0], a[1], a[2], a[3]);
        }
    } else {
        int wb2 = bid - 384;
        int mat = wb2 >> 6, t64 = wb2 & 63;
        int n0 = (t64 >> 3) * 64, k0 = (t64 & 7) * 64;
        const float* W = (mat == 0) ? Wq : (mat == 1) ? Wk : (mat == 2) ? Wv : Wo;
        int r = tid >> 2;
        #pragma unroll
        for (int i = 0; i < 4; i++) {
            int c = ((tid & 3) + 4*i) * 4;
            *(float4*)&Ts[r][c] = *(const float4*)(W + (size_t)(n0 + r)*HIDD + k0 + c);
        }
        __syncthreads();
        #pragma unroll
        for (int i = 0; i < 8; i++) {
            int f = (tid >> 5) + 8*i;
            int nb = f >> 3, kk = f & 7;
            unsigned b[2];
            #pragma unroll
            for (int rg = 0; rg < 2; rg++) {
                int nn = lane >> 2;
                int kb = (lane & 3) + 4*rg;
                b[rg] = f2tf32(Ts[nb*8 + nn][kk*8 + kb]);
            }
            size_t idx = ((size_t)(mat*64 + (n0 >> 3) + nb) * 64 + (k0 >> 3) + kk) * 64 + lane*2;
            *(uint2*)&g_wf[idx] = make_uint2(b[0], b[1]);
        }
    }
}

// ============================================================
// Pipelined 64x64x512 GEMM core (R5-proven): cp.async double-buffered.
// ============================================================
__device__ __forceinline__ void gemm_pipe(
    const unsigned* __restrict__ abase, const unsigned* __restrict__ wbase,
    unsigned* sA, unsigned* sW, float facc[4][4],
    int tid, int lane, int wr, int wc)
{
    auto stage = [&](int c, int buf) {
        #pragma unroll
        for (int rblk = 0; rblk < 4; rblk++) {
            unsigned dst = (unsigned)__cvta_generic_to_shared(sA + buf*4096 + rblk*1024 + tid*4);
            cp16(dst, abase + (size_t)(rblk*64 + c*8)*128 + tid*4);
        }
        #pragma unroll
        for (int s = 0; s < 4; s++) {
            int idx = tid + 256*s;
            int nb = idx >> 7, rem = idx & 127;
            unsigned dst = (unsigned)__cvta_generic_to_shared(sW + buf*4096 + nb*512 + rem*4);
            cp16(dst, wbase + (size_t)(nb*64 + c*8)*64 + rem*4);
        }
        CP_COMMIT;
    };

    stage(0, 0);
    for (int c = 0; c < 8; c++) {
        __syncthreads();
        if (c + 1 < 8) { stage(c + 1, (c + 1) & 1); CP_WAIT1; }
        else           { CP_WAIT0; }
        __syncthreads();
        const unsigned* A = sA + (c & 1) * 4096;
        const unsigned* W = sW + (c & 1) * 4096;
        #pragma unroll
        for (int kk = 0; kk < 8; kk++) {
            uint4 aa = *(const uint4*)(A + wr*1024 + kk*128 + lane*4);
            #pragma unroll
            for (int nt = 0; nt < 4; nt++) {
                uint2 bb = *(const uint2*)(W + (wc*4 + nt)*512 + kk*64 + lane*2);
                mma_tf32(facc[nt], aa, bb);
            }
        }
    }
}

// ============================================================
// Kernel 1: Q/K/V projections (pipelined GEMM + frag scatter)
// grid (8 heads, 48 m-tiles, 3 matrices), block 256
// ============================================================
__global__ __launch_bounds__(256) void qkv_kernel()
{
    extern __shared__ unsigned dsm[];
    unsigned* sA = dsm;           // 2 x 4096
    unsigned* sW = dsm + 8192;    // 2 x 4096

    int h = blockIdx.x, m0 = blockIdx.y * 64, z = blockIdx.z;
    int tid = threadIdx.x, lane = tid & 31, wid = tid >> 5;
    int wr = wid >> 1, wc = wid & 1;

    float facc[4][4] = {};
    gemm_pipe(g_af + (size_t)(m0 >> 4)*64*128,
              g_wf + (size_t)(z*64 + h*8)*64*64,
              sA, sW, facc, tid, lane, wr, wc);

    unsigned* outp = (z == 0) ? g_qf : ((z == 1) ? g_kf : g_vf);
    int q2 = lane & 3, r4 = lane >> 2;
    #pragma unroll
    for (int nt = 0; nt < 4; nt++) {
        #pragma unroll
        for (int hi = 0; hi < 2; hi++) {
            #pragma unroll
            for (int j = 0; j < 2; j++) {
                unsigned tv = f2tf32(facc[nt][2*hi + j]);
                int d = wc*32 + nt*8 + 2*q2 + j;
                int rtile = 16*wr + r4 + 8*hi;
                size_t idx;
                if (z == 0) {                   // Q: A-frag
                    int rr = rtile & 15;
                    idx = ((size_t)(h*192 + (m0 >> 4) + wr)*8 + (d >> 3))*128
                        + (size_t)(4*(rr & 7) + (d & 3))*4 + (rr >> 3) + 2*((d >> 2) & 1);
                } else if (z == 1) {            // K: B-frag (n=key, k=d)
                    int nb = rtile >> 3;
                    idx = (size_t)(h*48 + (m0 >> 6))*4096
                        + ((size_t)(nb*8 + (d >> 3))*32 + 4*(rtile & 7) + (d & 3))*2
                        + ((d >> 2) & 1);
                } else {                        // V: B-frag (n=d, k=key)
                    int db = d >> 3, kkv = rtile >> 3;
                    idx = (size_t)(h*48 + (m0 >> 6))*4096
                        + ((size_t)(db*8 + kkv)*32 + 4*(d & 7) + (rtile & 3))*2
                        + ((rtile >> 2) & 1);
                }
                outp[idx] = tv;
            }
        }
    }
}

// ============================================================
// Kernel 2: attention (R5 structure) with HEAVY-FIRST block order.
// grid 384 linear: class c = bid/64 (nj = 6-c, heaviest first),
// within class: h = bid%8, bq = (bid%64)/8.
// ============================================================
__global__ __launch_bounds__(256) void attn_kernel(float* __restrict__ w_out)
{
    extern __shared__ unsigned dsm[];
    unsigned* KV = dsm;                               // 2 bufs x 8192 (K | V)
    float (*Ps)[68] = (float(*)[68])(dsm + 16384);
    float* ls  = (float*)(dsm + 16384) + 64*68;
    float* lrl = ls + 64;

    int tid = threadIdx.x, lane = tid & 31, wid = tid >> 5;
    int wr = wid >> 1, wc = wid & 1;

    // heavy-first mapping
    int bid = blockIdx.x;
    int c   = bid >> 6;            // 0..5, class
    int nj  = 6 - c;               // valid 64-col j-tiles per batch (6 = heaviest)
    int e   = bid & 63;
    int h   = e & 7, bq = e >> 3;
    int s0  = (nj - 1) * 64;
    int r0  = bq * Ss + s0;
    int nv  = 8 * nj;

    int q2 = lane & 3, r4 = lane >> 2;
    int rlo = 16*wr + r4;
    int lrr = tid >> 4, lcc = (tid & 15) * 4;

    if (tid < 64) ls[tid] = 0.f;

    // Q fragments resident in registers
    uint4 qa[8];
    const unsigned* qb = g_qf + (size_t)((h*192 + (r0 >> 4) + wr)*8)*128;
    #pragma unroll
    for (int kk = 0; kk < 8; kk++) qa[kk] = *(const uint4*)(qb + kk*128 + lane*4);

    // masked tiles: zero w-writes up front
    for (int kb = 0; kb < 8; kb++)
        for (int j = nj; j < 6; j++) {
            size_t wrow = ((size_t)((bq*NHh + h)*Bb + kb)) * Ss;
            float4 z = make_float4(0.f, 0.f, 0.f, 0.f);
            #pragma unroll
            for (int i = 0; i < 4; i++)
                *(float4*)(w_out + (wrow + s0 + lrr + 16*i) * Ss + j*64 + lcc) = z;
        }

    auto stageK = [&](int v, int buf) {
        int kt = (v/nj)*6 + (v % nj);
        const unsigned* src = g_kf + (size_t)(h*48 + kt)*4096;
        #pragma unroll
        for (int s = 0; s < 4; s++) {
            unsigned dst = (unsigned)__cvta_generic_to_shared(KV + buf*8192 + s*1024 + tid*4);
            cp16(dst, src + s*1024 + tid*4);
        }
        CP_COMMIT;
    };
    auto stageKV = [&](int v, int buf) {
        int kt = (v/nj)*6 + (v % nj);
        const unsigned* ks = g_kf + (size_t)(h*48 + kt)*4096;
        const unsigned* vs = g_vf + (size_t)(h*48 + kt)*4096;
        #pragma unroll
        for (int s = 0; s < 4; s++) {
            unsigned dk = (unsigned)__cvta_generic_to_shared(KV + buf*8192 + s*1024 + tid*4);
            unsigned dv = (unsigned)__cvta_generic_to_shared(KV + buf*8192 + 4096 + s*1024 + tid*4);
            cp16(dk, ks + s*1024 + tid*4);
            cp16(dv, vs + s*1024 + tid*4);
        }
        CP_COMMIT;
    };

    // -------- phase A: row sums --------
    stageK(0, 0);
    for (int v = 0; v < nv; v++) {
        __syncthreads();
        if (v + 1 < nv) { stageK(v + 1, (v + 1) & 1); CP_WAIT1; }
        else            { CP_WAIT0; }
        __syncthreads();
        const unsigned* Kf = KV + (v & 1)*8192;
        int kp0 = (v % nj) * 64;

        float sacc[4][4] = {};
        #pragma unroll
        for (int nt = 0; nt < 4; nt++) {
            int nb = wc*4 + nt;
            #pragma unroll
            for (int kk = 0; kk < 8; kk++) {
                uint2 bb = *(const uint2*)(Kf + (nb*8 + kk)*64 + lane*2);
                mma_tf32(sacc[nt], qa[kk], bb);
            }
        }

        bool diag = (kp0 == s0);
        float s_lo = 0.f, s_hi = 0.f;
        #pragma unroll
        for (int nt = 0; nt < 4; nt++) {
            int cb = wc*32 + nt*8 + 2*q2;
            float p0 = __expf(sacc[nt][0] * ISCALE);
            float p1 = __expf(sacc[nt][1] * ISCALE);
            float p2 = __expf(sacc[nt][2] * ISCALE);
            float p3 = __expf(sacc[nt][3] * ISCALE);
            if (diag) {
                if (cb     > rlo)     p0 = 0.f;
                if (cb + 1 > rlo)     p1 = 0.f;
                if (cb     > rlo + 8) p2 = 0.f;
                if (cb + 1 > rlo + 8) p3 = 0.f;
            }
            s_lo += p0 + p1; s_hi += p2 + p3;
        }
        s_lo += __shfl_xor_sync(0xffffffffu, s_lo, 1);
        s_lo += __shfl_xor_sync(0xffffffffu, s_lo, 2);
        s_hi += __shfl_xor_sync(0xffffffffu, s_hi, 1);
        s_hi += __shfl_xor_sync(0xffffffffu, s_hi, 2);
        if (q2 == 0) { atomicAdd(&ls[rlo], s_lo); atomicAdd(&ls[rlo + 8], s_hi); }
    }

    __syncthreads();
    if (tid < 64) lrl[tid] = -__logf(ls[tid]);
    __syncthreads();
    float la = lrl[rlo], lb = lrl[rlo + 8];

    float cacc[4][4] = {};

    // -------- phase B: normalized w + PV --------
    stageKV(0, 0);
    for (int v = 0; v < nv; v++) {
        __syncthreads();
        if (v + 1 < nv) { stageKV(v + 1, (v + 1) & 1); CP_WAIT1; }
        else            { CP_WAIT0; }
        __syncthreads();
        const unsigned* Kf = KV + (v & 1)*8192;
        const unsigned* Vf = Kf + 4096;
        int kp0 = (v % nj) * 64, kb2 = v / nj;
        size_t wrow = ((size_t)((bq*NHh + h)*Bb + kb2)) * Ss;

        float sacc[4][4] = {};
        #pragma unroll
        for (int nt = 0; nt < 4; nt++) {
            int nb = wc*4 + nt;
            #pragma unroll
            for (int kk = 0; kk < 8; kk++) {
                uint2 bb = *(const uint2*)(Kf + (nb*8 + kk)*64 + lane*2);
                mma_tf32(sacc[nt], qa[kk], bb);
            }
        }

        bool diag = (kp0 == s0);
        #pragma unroll
        for (int nt = 0; nt < 4; nt++) {
            int cb = wc*32 + nt*8 + 2*q2;
            float p0 = __expf(fmaf(sacc[nt][0], ISCALE, la));
            float p1 = __expf(fmaf(sacc[nt][1], ISCALE, la));
            float p2 = __expf(fmaf(sacc[nt][2], ISCALE, lb));
            float p3 = __expf(fmaf(sacc[nt][3], ISCALE, lb));
            if (diag) {
                if (cb     > rlo)     p0 = 0.f;
                if (cb + 1 > rlo)     p1 = 0.f;
                if (cb     > rlo + 8) p2 = 0.f;
                if (cb + 1 > rlo + 8) p3 = 0.f;
            }
            *(float2*)&Ps[rlo][cb]     = make_float2(p0, p1);
            *(float2*)&Ps[rlo + 8][cb] = make_float2(p2, p3);
        }
        __syncthreads();

        // coalesced normalized w write
        #pragma unroll
        for (int i = 0; i < 4; i++)
            *(float4*)(w_out + (wrow + s0 + lrr + 16*i) * Ss + kp0 + lcc) =
                *(float4*)&Ps[lrr + 16*i][lcc];

        // ctx += P V  (P as raw fp32 bits -> tf32 truncation)
        #pragma unroll
        for (int kk = 0; kk < 8; kk++) {
            int k0 = kk * 8;
            uint4 pa;
            pa.x = __float_as_uint(Ps[rlo    ][k0 + q2]);
            pa.y = __float_as_uint(Ps[rlo + 8][k0 + q2]);
            pa.z = __float_as_uint(Ps[rlo    ][k0 + 4 + q2]);
            pa.w = __float_as_uint(Ps[rlo + 8][k0 + 4 + q2]);
            #pragma unroll
            for (int nt = 0; nt < 4; nt++) {
                uint2 bb = *(const uint2*)(Vf + ((wc*4 + nt)*8 + kk)*64 + lane*2);
                mma_tf32(cacc[nt], pa, bb);
            }
        }
    }

    // ctx epilogue -> A-frag layout (already normalized)
    int rblkg = (r0 >> 4) + wr;
    #pragma unroll
    for (int nt = 0; nt < 4; nt++) {
        size_t kkg = (size_t)(h*8 + wc*4 + nt);
        #pragma unroll
        for (int hi = 0; hi < 2; hi++) {
            #pragma unroll
            for (int j = 0; j < 2; j++) {
                int kbit = 2*q2 + j;
                int word = (4*r4 + (kbit & 3))*4 + hi + 2*((kbit >> 2) & 1);
                g_cf[((size_t)rblkg*64 + kkg)*128 + word] = f2tf32(cacc[nt][2*hi + j]);
            }
        }
    }
}

// ============================================================
// Kernel 3: out_pre = ctx @ Wo^T + enc -> g_tmp (pipelined GEMM)
// grid (8 n-tiles, 48 m-tiles), block 256
// ============================================================
__global__ __launch_bounds__(256) void out_kernel(const float* __restrict__ enc)
{
    extern __shared__ unsigned dsm[];
    unsigned* sA = dsm;
    unsigned* sW = dsm + 8192;

    int n0 = blockIdx.x * 64, m0 = blockIdx.y * 64;
    int tid = threadIdx.x, lane = tid & 31, wid = tid >> 5;
    int wr = wid >> 1, wc = wid & 1;

    float facc[4][4] = {};
    gemm_pipe(g_cf + (size_t)(m0 >> 4)*64*128,
              g_wf + (size_t)(3*64 + (n0 >> 3))*64*64,
              sA, sW, facc, tid, lane, wr, wc);

    int q2 = lane & 3, r4 = lane >> 2;
    #pragma unroll
    for (int nt = 0; nt < 4; nt++) {
        #pragma unroll
        for (int hi = 0; hi < 2; hi++) {
            int row = m0 + 16*wr + r4 + 8*hi;
            int col = n0 + wc*32 + nt*8 + 2*q2;
            float2 e2 = *(const float2*)(enc + (size_t)row * HIDD + col);
            float2 o = make_float2(facc[nt][2*hi] + e2.x, facc[nt][2*hi + 1] + e2.y);
            *(float2*)(g_tmp + (size_t)row * HIDD + col) = o;
        }
    }
}

// ============================================================
// Kernel 4: per-row LayerNorm -> d_out[0 : R*HID]
// ============================================================
__global__ __launch_bounds__(256) void ln_kernel(
    const float* __restrict__ gamma,
    const float* __restrict__ beta,
    float* __restrict__ out)
{
    int r = blockIdx.x;
    int t = threadIdx.x;
    const float* x = g_tmp + (size_t)r * HIDD;
    float v0 = x[t], v1 = x[t + 256];

    __shared__ float red[256];
    red[t] = v0 + v1;
    __syncthreads();
    #pragma unroll
    for (int o = 128; o > 0; o >>= 1) {
        if (t < o) red[t] += red[t + o];
        __syncthreads();
    }
    float mu = red[0] * (1.0f / HIDD);
    __syncthreads();

    float d0 = v0 - mu, d1 = v1 - mu;
    red[t] = d0*d0 + d1*d1;
    __syncthreads();
    #pragma unroll
    for (int o = 128; o > 0; o >>= 1) {
        if (t < o) red[t] += red[t + o];
        __syncthreads();
    }
    float var = red[0] * (1.0f / HIDD);
    float rs = rsqrtf(var + 1e-6f);

    out[(size_t)r * HIDD + t]       = d0 * rs * gamma[t]       + beta[t];
    out[(size_t)r * HIDD + t + 256] = d1 * rs * gamma[t + 256] + beta[t + 256];
}

// ============================================================
// launch
// ============================================================
extern "C" void kernel_launch(void* const* d_in, const int* in_sizes, int n_in,
                              void* d_out, int out_size)
{
    const float* enc   = (const float*)d_in[0];
    // d_in[1] = mask (int32 tril) — reproduced analytically
    const float* Wq    = (const float*)d_in[2];
    const float* Wk    = (const float*)d_in[3];
    const float* Wv    = (const float*)d_in[4];
    const float* Wo    = (const float*)d_in[5];
    const float* gamma = (const float*)d_in[6];
    const float* beta  = (const float*)d_in[7];

    float* out = (float*)d_out;                  // (B,S,HID)
    float* w   = out + (size_t)RR * HIDD;        // (B,NH,B,S,S)

    const int gemm_smem = 16384 * 4;                         // 64 KB
    const int attn_smem = 16384 * 4 + (64*68 + 128) * 4;     // 83456 B
    cudaFuncSetAttribute(qkv_kernel,  cudaFuncAttributeMaxDynamicSharedMemorySize, gemm_smem);
    cudaFuncSetAttribute(out_kernel,  cudaFuncAttributeMaxDynamicSharedMemorySize, gemm_smem);
    cudaFuncSetAttribute(attn_kernel, cudaFuncAttributeMaxDynamicSharedMemorySize, attn_smem);

    prep_kernel<<<640, 256>>>(enc, Wq, Wk, Wv, Wo);
    qkv_kernel<<<dim3(8, 48, 3), 256, gemm_smem>>>();
    attn_kernel<<<384, 256, attn_smem>>>(w);
    out_kernel<<<dim3(8, 48), 256, gemm_smem>>>(enc);
    ln_kernel<<<RR, 256>>>(gamma, beta, out);
}